// round 6
// baseline (speedup 1.0000x reference)
#include <cuda_runtime.h>

using u64 = unsigned long long;

// ---------------- problem constants (fixed shapes) -------------------------
constexpr int Bn = 4;
constexpr int Nn = 8192;
constexpr int Cc = 32;
constexpr int M2 = 8192;
constexpr int M3 = 4096;
constexpr int M4 = 2048;
constexpr int MM = 4096;

constexpr int Q     = 4;           // queries per lane
constexpr int QPB   = 128;         // queries per block (32 lanes * Q)
constexpr int PARTS = 8;           // warps per block (candidate partitions)
constexpr int NT    = 256;
constexpr float BIG = 3.0e38f;

// ---------------- device scratch: interleaved group records ----------------
// interp sets: per 4-candidate group, 20 floats [x4|y4|z4|kk4|fv4] = 80 B
// mask set:    per 4-candidate group, 16 floats [x4|y4|z4|kk4]    = 64 B
__device__ __align__(16) float g2buf[Bn * M2 * 5];
__device__ __align__(16) float g3buf[Bn * M3 * 5];
__device__ __align__(16) float g4buf[Bn * M4 * 5];
__device__ __align__(16) float gmbuf[Bn * MM * 4];

// ---------------- packed f32x2 helpers --------------------------------------
__device__ __forceinline__ u64 ffma2u(u64 a, u64 b, u64 c) {
    u64 r;
    asm("fma.rn.f32x2 %0, %1, %2, %3;" : "=l"(r) : "l"(a), "l"(b), "l"(c));
    return r;
}
__device__ __forceinline__ u64 fadd2u(u64 a, u64 b) {
    u64 r;
    asm("add.rn.f32x2 %0, %1, %2;" : "=l"(r) : "l"(a), "l"(b));
    return r;
}
__device__ __forceinline__ float lo_(u64 v) { return __uint_as_float((unsigned)v); }
__device__ __forceinline__ float hi_(u64 v) { return __uint_as_float((unsigned)(v >> 32)); }
__device__ __forceinline__ u64 dup2(float x) {
    unsigned b = __float_as_uint(x);
    return ((u64)b << 32) | (u64)b;
}

// ---------------- precompute: pack into interleaved records -----------------
__global__ void precompute_kernel(
    const float* __restrict__ known2, const float* __restrict__ feats2,
    const float* __restrict__ known3, const float* __restrict__ feats3,
    const float* __restrict__ known4, const float* __restrict__ feats4,
    const float* __restrict__ matchp,
    const float* __restrict__ w_fc, const float* __restrict__ w_cls)
{
    __shared__ float sv[96];                    // v = w_cls @ w_fc (per-block)
    int t = threadIdx.x;
    if (t < 96) {
        float acc = 0.f;
#pragma unroll
        for (int k = 0; k < 64; k++) acc = fmaf(w_cls[k], w_fc[k * 96 + t], acc);
        sv[t] = acc;
    }
    __syncthreads();

    int idx = blockIdx.x * NT + t;
    constexpr int A = Bn * M2;
    constexpr int B = A + Bn * M3;
    constexpr int C = B + Bn * M4;
    constexpr int D = C + Bn * MM;

    const float* known; const float* feats; float* buf; int i, voff;
    if (idx < A)      { known = known2; feats = feats2; buf = g2buf; i = idx;     voff = 0;  }
    else if (idx < B) { known = known3; feats = feats3; buf = g3buf; i = idx - A; voff = 32; }
    else if (idx < C) { known = known4; feats = feats4; buf = g4buf; i = idx - B; voff = 64; }
    else if (idx < D) {
        int i2 = idx - C;
        float x = matchp[3 * i2 + 0];
        float y = matchp[3 * i2 + 1];
        float z = matchp[3 * i2 + 2];
        float kk = __fadd_rn(__fadd_rn(__fmul_rn(x, x), __fmul_rn(y, y)), __fmul_rn(z, z));
        int base = (i2 >> 2) * 16 + (i2 & 3);
        gmbuf[base + 0] = x; gmbuf[base + 4] = y;
        gmbuf[base + 8] = z; gmbuf[base + 12] = kk;
        return;
    } else return;

    float x = known[3 * i + 0];
    float y = known[3 * i + 1];
    float z = known[3 * i + 2];
    // same rounding order as jnp.sum(known*known, -1)
    float kk = __fadd_rn(__fadd_rn(__fmul_rn(x, x), __fmul_rn(y, y)), __fmul_rn(z, z));

    float acc = 0.f;
    const float4* f4 = reinterpret_cast<const float4*>(feats + (size_t)i * Cc);
#pragma unroll
    for (int j = 0; j < 8; j++) {
        float4 tt = f4[j];
        acc = fmaf(tt.x, sv[voff + 4 * j + 0], acc);
        acc = fmaf(tt.y, sv[voff + 4 * j + 1], acc);
        acc = fmaf(tt.z, sv[voff + 4 * j + 2], acc);
        acc = fmaf(tt.w, sv[voff + 4 * j + 3], acc);
    }
    int base = (i >> 2) * 20 + (i & 3);
    buf[base + 0]  = x;  buf[base + 4]  = y;
    buf[base + 8]  = z;  buf[base + 12] = kk;
    buf[base + 16] = acc;
}

// ---------------- branchless sorted top-3 insert (strict <, stable) ---------
__device__ __forceinline__ void ins_nb(float e, float fv, float t[3], float f[3]) {
    bool p2 = e < t[2];
    bool p1 = e < t[1];
    bool p0 = e < t[0];
    t[2] = p1 ? t[1] : (p2 ? e  : t[2]);
    f[2] = p1 ? f[1] : (p2 ? fv : f[2]);
    t[1] = p0 ? t[0] : (p1 ? e  : t[1]);
    f[1] = p0 ? f[0] : (p1 ? fv : f[1]);
    t[0] = p0 ? e  : t[0];
    f[0] = p0 ? fv : f[0];
}

// gated/branchy version for the cold merge path
__device__ __forceinline__ void try_ins(float e, float fv, float t[3], float f[3]) {
    if (e < t[2]) ins_nb(e, fv, t, f);
}

// ---------------- interp scan: top-3 of d = (qq+kk) - 2*dot -----------------
// rounding order matches reference: s = qq+kk, then fma x, y, z
__device__ __forceinline__ void scan_set(
    const float* __restrict__ buf, int grp0, int Mg,
    const u64 c2x[Q], const u64 c2y[Q], const u64 c2z[Q], const u64 qq2[Q],
    float t[Q][3], float f[Q][3])
{
#pragma unroll
    for (int j = 0; j < Q; j++) {
        t[j][0] = t[j][1] = t[j][2] = BIG;
        f[j][0] = f[j][1] = f[j][2] = 0.f;
    }
    const char* p = reinterpret_cast<const char*>(buf) + (size_t)grp0 * 80;
#pragma unroll 2
    for (int g = 0; g < Mg; g++, p += 80) {
        ulonglong2 X = __ldg(reinterpret_cast<const ulonglong2*>(p));
        ulonglong2 Y = __ldg(reinterpret_cast<const ulonglong2*>(p + 16));
        ulonglong2 Z = __ldg(reinterpret_cast<const ulonglong2*>(p + 32));
        ulonglong2 W = __ldg(reinterpret_cast<const ulonglong2*>(p + 48));
        float4     F = __ldg(reinterpret_cast<const float4*>(p + 64));
#pragma unroll
        for (int j = 0; j < Q; j++) {
            u64 dl = ffma2u(c2x[j], X.x, fadd2u(qq2[j], W.x));
            dl = ffma2u(c2y[j], Y.x, dl);
            dl = ffma2u(c2z[j], Z.x, dl);
            u64 dh = ffma2u(c2x[j], X.y, fadd2u(qq2[j], W.y));
            dh = ffma2u(c2y[j], Y.y, dh);
            dh = ffma2u(c2z[j], Z.y, dh);
            float d0 = lo_(dl), d1 = hi_(dl), d2 = lo_(dh), d3 = hi_(dh);
            float m = fminf(fminf(d0, d1), fminf(d2, d3));
            if (m < t[j][2]) {                    // branchless body, one gate
                ins_nb(d0, F.x, t[j], f[j]);
                ins_nb(d1, F.y, t[j], f[j]);
                ins_nb(d2, F.z, t[j], f[j]);
                ins_nb(d3, F.w, t[j], f[j]);
            }
        }
    }
}

// ---------------- mask scan: any(d2 < 0.25), margin + exact recheck ---------
__device__ __forceinline__ void scan_mask(
    const float* __restrict__ buf, int grp0, int Mg,
    const u64 c2x[Q], const u64 c2y[Q], const u64 c2z[Q], const u64 qq2[Q],
    bool found[Q])
{
    float tf[Q], qx[Q], qy[Q], qz[Q], qqv[Q];
#pragma unroll
    for (int j = 0; j < Q; j++) {
        found[j] = false;
        qqv[j] = lo_(qq2[j]);
        tf[j]  = 0.3125f - qqv[j];               // e < 0.25 + 0.0625 margin
        qx[j]  = -0.5f * lo_(c2x[j]);            // exact (pow2 scale)
        qy[j]  = -0.5f * lo_(c2y[j]);
        qz[j]  = -0.5f * lo_(c2z[j]);
    }
    const char* p = reinterpret_cast<const char*>(buf) + (size_t)grp0 * 64;
#pragma unroll 2
    for (int g = 0; g < Mg; g++, p += 64) {
        ulonglong2 X = __ldg(reinterpret_cast<const ulonglong2*>(p));
        ulonglong2 Y = __ldg(reinterpret_cast<const ulonglong2*>(p + 16));
        ulonglong2 Z = __ldg(reinterpret_cast<const ulonglong2*>(p + 32));
        ulonglong2 W = __ldg(reinterpret_cast<const ulonglong2*>(p + 48));
#pragma unroll
        for (int j = 0; j < Q; j++) {
            // fast path: e = kk - 2*dot (qq deferred; protected by margin)
            u64 el = ffma2u(c2x[j], X.x, ffma2u(c2y[j], Y.x, ffma2u(c2z[j], Z.x, W.x)));
            u64 eh = ffma2u(c2x[j], X.y, ffma2u(c2y[j], Y.y, ffma2u(c2z[j], Z.y, W.y)));
            float m = fminf(fminf(lo_(el), hi_(el)), fminf(lo_(eh), hi_(eh)));
            if (m < tf[j]) {                      // rare: exact recheck
                float cx[4] = { lo_(X.x), hi_(X.x), lo_(X.y), hi_(X.y) };
                float cy[4] = { lo_(Y.x), hi_(Y.x), lo_(Y.y), hi_(Y.y) };
                float cz[4] = { lo_(Z.x), hi_(Z.x), lo_(Z.y), hi_(Z.y) };
                float cw[4] = { lo_(W.x), hi_(W.x), lo_(W.y), hi_(W.y) };
#pragma unroll
                for (int c = 0; c < 4; c++) {
                    // bit-exact reference-mimic rounding
                    float dot = __fadd_rn(__fadd_rn(__fmul_rn(qx[j], cx[c]),
                                                    __fmul_rn(qy[j], cy[c])),
                                          __fmul_rn(qz[j], cz[c]));
                    float d = __fsub_rn(__fadd_rn(qqv[j], cw[c]),
                                        __fadd_rn(dot, dot));
                    if (d < 0.25f) found[j] = true;
                }
            }
        }
    }
}

// ---------------- merge 24 partial top-3 entries -----------------------------
__device__ __forceinline__ float merge_one(const float2* __restrict__ ent) {
    float t[3] = {BIG, BIG, BIG}, f[3] = {0.f, 0.f, 0.f};
#pragma unroll
    for (int k = 0; k < PARTS * 3; k++) {
        float2 c = ent[k];
        try_ins(c.x, c.y, t, f);
    }
    float d0 = fmaxf(t[0], 0.f);
    float d1 = fmaxf(t[1], 0.f);
    float d2 = fmaxf(t[2], 0.f);
    float r0 = 1.f / (d0 + 1e-8f);
    float r1 = 1.f / (d1 + 1e-8f);
    float r2 = 1.f / (d2 + 1e-8f);
    return fmaf(r0, f[0], fmaf(r1, f[1], r2 * f[2])) / (r0 + r1 + r2);
}

// ---------------- fused main kernel -----------------------------------------
__global__ void __launch_bounds__(NT, 3)
fused_kernel(const float* __restrict__ pts, float* __restrict__ out) {
    __shared__ float2 s_m[QPB * PARTS * 3];      // 24 KB merge scratch

    const int tid  = threadIdx.x;
    const int lane = tid & 31;
    const int part = tid >> 5;                   // warp id == candidate part
    const int b    = (blockIdx.x * QPB) >> 13;   // batch

    u64 c2x[Q], c2y[Q], c2z[Q], qq2[Q];
#pragma unroll
    for (int j = 0; j < Q; j++) {
        int gq = blockIdx.x * QPB + j * 32 + lane;
        float x = pts[3 * gq + 0];
        float y = pts[3 * gq + 1];
        float z = pts[3 * gq + 2];
        float qq = __fadd_rn(__fadd_rn(__fmul_rn(x, x), __fmul_rn(y, y)),
                             __fmul_rn(z, z));
        c2x[j] = dup2(-2.f * x);
        c2y[j] = dup2(-2.f * y);
        c2z[j] = dup2(-2.f * z);
        qq2[j] = dup2(qq);
    }

    float pred = 0.f;                            // meaningful for tid < QPB
    float t[Q][3], f[Q][3];

    const float* sb[3] = { g2buf, g3buf, g4buf };
    const int    sM[3] = { M2, M3, M4 };

#pragma unroll 1
    for (int s = 0; s < 3; s++) {
        const int Mg = sM[s] / (4 * PARTS);      // groups per part
        const int grp0 = (b * sM[s]) / 4 + part * Mg;
        scan_set(sb[s], grp0, Mg, c2x, c2y, c2z, qq2, t, f);
#pragma unroll
        for (int j = 0; j < Q; j++) {
            int q = j * 32 + lane;
            int bse = (q * PARTS + part) * 3;
            s_m[bse + 0] = make_float2(t[j][0], f[j][0]);
            s_m[bse + 1] = make_float2(t[j][1], f[j][1]);
            s_m[bse + 2] = make_float2(t[j][2], f[j][2]);
        }
        __syncthreads();
        if (tid < QPB) pred += merge_one(s_m + tid * PARTS * 3);
        __syncthreads();
    }

    bool found[Q];
    {
        const int Mg = MM / (4 * PARTS);
        const int grp0 = (b * MM) / 4 + part * Mg;
        scan_mask(gmbuf, grp0, Mg, c2x, c2y, c2z, qq2, found);
    }

    float* s_fl = reinterpret_cast<float*>(s_m);
#pragma unroll
    for (int j = 0; j < Q; j++)
        s_fl[(j * 32 + lane) * PARTS + part] = found[j] ? 1.f : 0.f;
    __syncthreads();
    if (tid < QPB) {
        float fl = 0.f;
#pragma unroll
        for (int k = 0; k < PARTS; k++) fl = fmaxf(fl, s_fl[tid * PARTS + k]);
        int gq = blockIdx.x * QPB + tid;
        out[gq] = pred;                          // pred_hm (B,N,1)
        out[Bn * Nn + gq] = fl;                  // gt_hm   (B,N)
    }
}

// ---------------- launch ----------------------------------------------------
extern "C" void kernel_launch(void* const* d_in, const int* in_sizes, int n_in,
                              void* d_out, int out_size) {
    (void)in_sizes; (void)n_in; (void)out_size;
    const float* pts    = (const float*)d_in[0];
    const float* known2 = (const float*)d_in[1];
    const float* feats2 = (const float*)d_in[2];
    const float* known3 = (const float*)d_in[3];
    const float* feats3 = (const float*)d_in[4];
    const float* known4 = (const float*)d_in[5];
    const float* feats4 = (const float*)d_in[6];
    const float* matchp = (const float*)d_in[7];
    const float* w_fc   = (const float*)d_in[8];
    const float* w_cls  = (const float*)d_in[9];
    float* out = (float*)d_out;

    constexpr int total = Bn * (M2 + M3 + M4 + MM);
    precompute_kernel<<<(total + NT - 1) / NT, NT>>>(
        known2, feats2, known3, feats3, known4, feats4, matchp, w_fc, w_cls);
    fused_kernel<<<(Bn * Nn) / QPB, NT>>>(pts, out);
}

// round 7
// speedup vs baseline: 1.5342x; 1.5342x over previous
#include <cuda_runtime.h>

using u64 = unsigned long long;

// ---------------- problem constants (fixed shapes) -------------------------
constexpr int Bn = 4;
constexpr int Nn = 8192;
constexpr int Cc = 32;
constexpr int M2 = 8192;
constexpr int M3 = 4096;
constexpr int M4 = 2048;
constexpr int MM = 4096;

constexpr int Q     = 2;           // queries per lane
constexpr int QPB   = 64;          // queries per block (32 lanes * Q)
constexpr int PARTS = 8;           // warps per block (candidate partitions)
constexpr int NT    = 256;
constexpr float BIG = 3.0e38f;

// ---------------- device scratch: interleaved group records ----------------
// interp sets: per 4-candidate group, 20 floats [x4|y4|z4|kk4|fv4] = 80 B
// mask set:    per 4-candidate group, 16 floats [x4|y4|z4|kk4]    = 64 B
__device__ __align__(16) float g2buf[Bn * M2 * 5];
__device__ __align__(16) float g3buf[Bn * M3 * 5];
__device__ __align__(16) float g4buf[Bn * M4 * 5];
__device__ __align__(16) float gmbuf[Bn * MM * 4];

// ---------------- packed f32x2 helpers --------------------------------------
__device__ __forceinline__ u64 ffma2u(u64 a, u64 b, u64 c) {
    u64 r;
    asm("fma.rn.f32x2 %0, %1, %2, %3;" : "=l"(r) : "l"(a), "l"(b), "l"(c));
    return r;
}
__device__ __forceinline__ u64 fadd2u(u64 a, u64 b) {
    u64 r;
    asm("add.rn.f32x2 %0, %1, %2;" : "=l"(r) : "l"(a), "l"(b));
    return r;
}
__device__ __forceinline__ float lo_(u64 v) { return __uint_as_float((unsigned)v); }
__device__ __forceinline__ float hi_(u64 v) { return __uint_as_float((unsigned)(v >> 32)); }
__device__ __forceinline__ u64 dup2(float x) {
    unsigned b = __float_as_uint(x);
    return ((u64)b << 32) | (u64)b;
}

// ---------------- precompute: pack into interleaved records -----------------
__global__ void precompute_kernel(
    const float* __restrict__ known2, const float* __restrict__ feats2,
    const float* __restrict__ known3, const float* __restrict__ feats3,
    const float* __restrict__ known4, const float* __restrict__ feats4,
    const float* __restrict__ matchp,
    const float* __restrict__ w_fc, const float* __restrict__ w_cls)
{
    __shared__ float sv[96];                    // v = w_cls @ w_fc (per-block)
    int t = threadIdx.x;
    if (t < 96) {
        float acc = 0.f;
#pragma unroll
        for (int k = 0; k < 64; k++) acc = fmaf(w_cls[k], w_fc[k * 96 + t], acc);
        sv[t] = acc;
    }
    __syncthreads();

    int idx = blockIdx.x * NT + t;
    constexpr int A = Bn * M2;
    constexpr int B = A + Bn * M3;
    constexpr int C = B + Bn * M4;
    constexpr int D = C + Bn * MM;

    const float* known; const float* feats; float* buf; int i, voff;
    if (idx < A)      { known = known2; feats = feats2; buf = g2buf; i = idx;     voff = 0;  }
    else if (idx < B) { known = known3; feats = feats3; buf = g3buf; i = idx - A; voff = 32; }
    else if (idx < C) { known = known4; feats = feats4; buf = g4buf; i = idx - B; voff = 64; }
    else if (idx < D) {
        int i2 = idx - C;
        float x = matchp[3 * i2 + 0];
        float y = matchp[3 * i2 + 1];
        float z = matchp[3 * i2 + 2];
        float kk = __fadd_rn(__fadd_rn(__fmul_rn(x, x), __fmul_rn(y, y)), __fmul_rn(z, z));
        int base = (i2 >> 2) * 16 + (i2 & 3);
        gmbuf[base + 0] = x; gmbuf[base + 4] = y;
        gmbuf[base + 8] = z; gmbuf[base + 12] = kk;
        return;
    } else return;

    float x = known[3 * i + 0];
    float y = known[3 * i + 1];
    float z = known[3 * i + 2];
    // same rounding order as jnp.sum(known*known, -1)
    float kk = __fadd_rn(__fadd_rn(__fmul_rn(x, x), __fmul_rn(y, y)), __fmul_rn(z, z));

    float acc = 0.f;
    const float4* f4 = reinterpret_cast<const float4*>(feats + (size_t)i * Cc);
#pragma unroll
    for (int j = 0; j < 8; j++) {
        float4 tt = f4[j];
        acc = fmaf(tt.x, sv[voff + 4 * j + 0], acc);
        acc = fmaf(tt.y, sv[voff + 4 * j + 1], acc);
        acc = fmaf(tt.z, sv[voff + 4 * j + 2], acc);
        acc = fmaf(tt.w, sv[voff + 4 * j + 3], acc);
    }
    int base = (i >> 2) * 20 + (i & 3);
    buf[base + 0]  = x;  buf[base + 4]  = y;
    buf[base + 8]  = z;  buf[base + 12] = kk;
    buf[base + 16] = acc;
}

// ---------------- top-3 maintenance (short branchy nest, rare) --------------
__device__ __forceinline__ void try_ins(float e, float fv, float t[3], float f[3]) {
    if (e < t[2]) {
        if (e < t[1]) {
            t[2] = t[1]; f[2] = f[1];
            if (e < t[0]) { t[1] = t[0]; f[1] = f[0]; t[0] = e; f[0] = fv; }
            else          { t[1] = e;    f[1] = fv; }
        } else { t[2] = e; f[2] = fv; }
    }
}

// ---------------- interp scan: top-3 of d = (qq+kk) - 2*dot -----------------
// rounding order matches reference: s = qq+kk, then fma x, y, z
__device__ __forceinline__ void scan_set(
    const float* __restrict__ buf, int grp0, int Mg,
    const u64 c2x[Q], const u64 c2y[Q], const u64 c2z[Q], const u64 qq2[Q],
    float t[Q][3], float f[Q][3])
{
#pragma unroll
    for (int j = 0; j < Q; j++) {
        t[j][0] = t[j][1] = t[j][2] = BIG;
        f[j][0] = f[j][1] = f[j][2] = 0.f;
    }
    const char* p = reinterpret_cast<const char*>(buf) + (size_t)grp0 * 80;
#pragma unroll 2
    for (int g = 0; g < Mg; g++, p += 80) {
        ulonglong2 X = __ldg(reinterpret_cast<const ulonglong2*>(p));
        ulonglong2 Y = __ldg(reinterpret_cast<const ulonglong2*>(p + 16));
        ulonglong2 Z = __ldg(reinterpret_cast<const ulonglong2*>(p + 32));
        ulonglong2 W = __ldg(reinterpret_cast<const ulonglong2*>(p + 48));
        float4     F = __ldg(reinterpret_cast<const float4*>(p + 64));
#pragma unroll
        for (int j = 0; j < Q; j++) {
            u64 dl = ffma2u(c2x[j], X.x, fadd2u(qq2[j], W.x));
            dl = ffma2u(c2y[j], Y.x, dl);
            dl = ffma2u(c2z[j], Z.x, dl);
            u64 dh = ffma2u(c2x[j], X.y, fadd2u(qq2[j], W.y));
            dh = ffma2u(c2y[j], Y.y, dh);
            dh = ffma2u(c2z[j], Z.y, dh);
            float d0 = lo_(dl), d1 = hi_(dl), d2 = lo_(dh), d3 = hi_(dh);
            float m = fminf(fminf(d0, d1), fminf(d2, d3));
            if (m < t[j][2]) {                    // rare after warm-up
                try_ins(d0, F.x, t[j], f[j]);
                try_ins(d1, F.y, t[j], f[j]);
                try_ins(d2, F.z, t[j], f[j]);
                try_ins(d3, F.w, t[j], f[j]);
            }
        }
    }
}

// ---------------- mask scan: any(d2 < 0.25), margin + exact recheck ---------
__device__ __forceinline__ void scan_mask(
    const float* __restrict__ buf, int grp0, int Mg,
    const u64 c2x[Q], const u64 c2y[Q], const u64 c2z[Q], const u64 qq2[Q],
    bool found[Q])
{
    float tf[Q], qx[Q], qy[Q], qz[Q], qqv[Q];
#pragma unroll
    for (int j = 0; j < Q; j++) {
        found[j] = false;
        qqv[j] = lo_(qq2[j]);
        tf[j]  = 0.3125f - qqv[j];               // e < 0.25 + 0.0625 margin
        qx[j]  = -0.5f * lo_(c2x[j]);            // exact (pow2 scale)
        qy[j]  = -0.5f * lo_(c2y[j]);
        qz[j]  = -0.5f * lo_(c2z[j]);
    }
    const char* p = reinterpret_cast<const char*>(buf) + (size_t)grp0 * 64;
#pragma unroll 2
    for (int g = 0; g < Mg; g++, p += 64) {
        ulonglong2 X = __ldg(reinterpret_cast<const ulonglong2*>(p));
        ulonglong2 Y = __ldg(reinterpret_cast<const ulonglong2*>(p + 16));
        ulonglong2 Z = __ldg(reinterpret_cast<const ulonglong2*>(p + 32));
        ulonglong2 W = __ldg(reinterpret_cast<const ulonglong2*>(p + 48));
#pragma unroll
        for (int j = 0; j < Q; j++) {
            // fast path: e = kk - 2*dot (qq deferred; protected by margin)
            u64 el = ffma2u(c2x[j], X.x, ffma2u(c2y[j], Y.x, ffma2u(c2z[j], Z.x, W.x)));
            u64 eh = ffma2u(c2x[j], X.y, ffma2u(c2y[j], Y.y, ffma2u(c2z[j], Z.y, W.y)));
            float m = fminf(fminf(lo_(el), hi_(el)), fminf(lo_(eh), hi_(eh)));
            if (m < tf[j]) {                      // rare: exact recheck
                float cx[4] = { lo_(X.x), hi_(X.x), lo_(X.y), hi_(X.y) };
                float cy[4] = { lo_(Y.x), hi_(Y.x), lo_(Y.y), hi_(Y.y) };
                float cz[4] = { lo_(Z.x), hi_(Z.x), lo_(Z.y), hi_(Z.y) };
                float cw[4] = { lo_(W.x), hi_(W.x), lo_(W.y), hi_(W.y) };
#pragma unroll
                for (int c = 0; c < 4; c++) {
                    // bit-exact reference-mimic rounding
                    float dot = __fadd_rn(__fadd_rn(__fmul_rn(qx[j], cx[c]),
                                                    __fmul_rn(qy[j], cy[c])),
                                          __fmul_rn(qz[j], cz[c]));
                    float d = __fsub_rn(__fadd_rn(qqv[j], cw[c]),
                                        __fadd_rn(dot, dot));
                    if (d < 0.25f) found[j] = true;
                }
            }
        }
    }
}

// ---------------- merge 24 partial top-3 entries -----------------------------
__device__ __forceinline__ float merge_one(const float2* __restrict__ ent) {
    float t[3] = {BIG, BIG, BIG}, f[3] = {0.f, 0.f, 0.f};
#pragma unroll
    for (int k = 0; k < PARTS * 3; k++) {
        float2 c = ent[k];
        try_ins(c.x, c.y, t, f);
    }
    float d0 = fmaxf(t[0], 0.f);
    float d1 = fmaxf(t[1], 0.f);
    float d2 = fmaxf(t[2], 0.f);
    float r0 = 1.f / (d0 + 1e-8f);
    float r1 = 1.f / (d1 + 1e-8f);
    float r2 = 1.f / (d2 + 1e-8f);
    return fmaf(r0, f[0], fmaf(r1, f[1], r2 * f[2])) / (r0 + r1 + r2);
}

// ---------------- fused main kernel -----------------------------------------
// grid = 512 blocks; with <=64 regs all 512 are co-resident (4 per SM): one wave
__global__ void __launch_bounds__(NT, 4)
fused_kernel(const float* __restrict__ pts, float* __restrict__ out) {
    __shared__ float2 s_m[QPB * PARTS * 3];      // 12 KB merge scratch

    const int tid  = threadIdx.x;
    const int lane = tid & 31;
    const int part = tid >> 5;                   // warp id == candidate part
    const int b    = (blockIdx.x * QPB) >> 13;   // batch

    u64 c2x[Q], c2y[Q], c2z[Q], qq2[Q];
#pragma unroll
    for (int j = 0; j < Q; j++) {
        int gq = blockIdx.x * QPB + j * 32 + lane;
        float x = pts[3 * gq + 0];
        float y = pts[3 * gq + 1];
        float z = pts[3 * gq + 2];
        float qq = __fadd_rn(__fadd_rn(__fmul_rn(x, x), __fmul_rn(y, y)),
                             __fmul_rn(z, z));
        c2x[j] = dup2(-2.f * x);
        c2y[j] = dup2(-2.f * y);
        c2z[j] = dup2(-2.f * z);
        qq2[j] = dup2(qq);
    }

    float pred = 0.f;                            // meaningful for tid < QPB
    float t[Q][3], f[Q][3];

    const float* sb[3] = { g2buf, g3buf, g4buf };
    const int    sM[3] = { M2, M3, M4 };

#pragma unroll 1
    for (int s = 0; s < 3; s++) {
        const int Mg = sM[s] / (4 * PARTS);      // groups per part
        const int grp0 = (b * sM[s]) / 4 + part * Mg;
        scan_set(sb[s], grp0, Mg, c2x, c2y, c2z, qq2, t, f);
#pragma unroll
        for (int j = 0; j < Q; j++) {
            int q = j * 32 + lane;
            int bse = (q * PARTS + part) * 3;
            s_m[bse + 0] = make_float2(t[j][0], f[j][0]);
            s_m[bse + 1] = make_float2(t[j][1], f[j][1]);
            s_m[bse + 2] = make_float2(t[j][2], f[j][2]);
        }
        __syncthreads();
        if (tid < QPB) pred += merge_one(s_m + tid * PARTS * 3);
        __syncthreads();
    }

    bool found[Q];
    {
        const int Mg = MM / (4 * PARTS);
        const int grp0 = (b * MM) / 4 + part * Mg;
        scan_mask(gmbuf, grp0, Mg, c2x, c2y, c2z, qq2, found);
    }

    float* s_fl = reinterpret_cast<float*>(s_m);
#pragma unroll
    for (int j = 0; j < Q; j++)
        s_fl[(j * 32 + lane) * PARTS + part] = found[j] ? 1.f : 0.f;
    __syncthreads();
    if (tid < QPB) {
        float fl = 0.f;
#pragma unroll
        for (int k = 0; k < PARTS; k++) fl = fmaxf(fl, s_fl[tid * PARTS + k]);
        int gq = blockIdx.x * QPB + tid;
        out[gq] = pred;                          // pred_hm (B,N,1)
        out[Bn * Nn + gq] = fl;                  // gt_hm   (B,N)
    }
}

// ---------------- launch ----------------------------------------------------
extern "C" void kernel_launch(void* const* d_in, const int* in_sizes, int n_in,
                              void* d_out, int out_size) {
    (void)in_sizes; (void)n_in; (void)out_size;
    const float* pts    = (const float*)d_in[0];
    const float* known2 = (const float*)d_in[1];
    const float* feats2 = (const float*)d_in[2];
    const float* known3 = (const float*)d_in[3];
    const float* feats3 = (const float*)d_in[4];
    const float* known4 = (const float*)d_in[5];
    const float* feats4 = (const float*)d_in[6];
    const float* matchp = (const float*)d_in[7];
    const float* w_fc   = (const float*)d_in[8];
    const float* w_cls  = (const float*)d_in[9];
    float* out = (float*)d_out;

    constexpr int total = Bn * (M2 + M3 + M4 + MM);
    precompute_kernel<<<(total + NT - 1) / NT, NT>>>(
        known2, feats2, known3, feats3, known4, feats4, matchp, w_fc, w_cls);
    fused_kernel<<<(Bn * Nn) / QPB, NT>>>(pts, out);
}

// round 8
// speedup vs baseline: 1.5367x; 1.0016x over previous
#include <cuda_runtime.h>

using u64 = unsigned long long;

// ---------------- problem constants (fixed shapes) -------------------------
constexpr int Bn = 4;
constexpr int Nn = 8192;
constexpr int Cc = 32;
constexpr int M2 = 8192;
constexpr int M3 = 4096;
constexpr int M4 = 2048;
constexpr int MM = 4096;

constexpr int Q     = 2;           // queries per lane
constexpr int QPB   = 64;          // queries per block (32 lanes * Q)
constexpr int PARTS = 8;           // warps per block (candidate partitions)
constexpr int NT    = 256;
constexpr float BIG = 3.0e38f;

// ---------------- device scratch: interleaved group records ----------------
// interp sets: per 4-candidate group, 20 floats [x4|y4|z4|kk4|fv4] = 80 B
// mask set:    per 4-candidate group, 16 floats [x4|y4|z4|kk4]    = 64 B
__device__ __align__(16) float g2buf[Bn * M2 * 5];
__device__ __align__(16) float g3buf[Bn * M3 * 5];
__device__ __align__(16) float g4buf[Bn * M4 * 5];
__device__ __align__(16) float gmbuf[Bn * MM * 4];

// ---------------- packed f32x2 helpers --------------------------------------
__device__ __forceinline__ u64 ffma2u(u64 a, u64 b, u64 c) {
    u64 r;
    asm("fma.rn.f32x2 %0, %1, %2, %3;" : "=l"(r) : "l"(a), "l"(b), "l"(c));
    return r;
}
__device__ __forceinline__ u64 fadd2u(u64 a, u64 b) {
    u64 r;
    asm("add.rn.f32x2 %0, %1, %2;" : "=l"(r) : "l"(a), "l"(b));
    return r;
}
__device__ __forceinline__ float lo_(u64 v) { return __uint_as_float((unsigned)v); }
__device__ __forceinline__ float hi_(u64 v) { return __uint_as_float((unsigned)(v >> 32)); }
__device__ __forceinline__ u64 dup2(float x) {
    unsigned b = __float_as_uint(x);
    return ((u64)b << 32) | (u64)b;
}

// ---------------- precompute: pack into interleaved records -----------------
__global__ void precompute_kernel(
    const float* __restrict__ known2, const float* __restrict__ feats2,
    const float* __restrict__ known3, const float* __restrict__ feats3,
    const float* __restrict__ known4, const float* __restrict__ feats4,
    const float* __restrict__ matchp,
    const float* __restrict__ w_fc, const float* __restrict__ w_cls)
{
    __shared__ float sv[96];                    // v = w_cls @ w_fc (per-block)
    int t = threadIdx.x;
    if (t < 96) {
        float acc = 0.f;
#pragma unroll
        for (int k = 0; k < 64; k++) acc = fmaf(w_cls[k], w_fc[k * 96 + t], acc);
        sv[t] = acc;
    }
    __syncthreads();

    int idx = blockIdx.x * NT + t;
    constexpr int A = Bn * M2;
    constexpr int B = A + Bn * M3;
    constexpr int C = B + Bn * M4;
    constexpr int D = C + Bn * MM;

    const float* known; const float* feats; float* buf; int i, voff;
    if (idx < A)      { known = known2; feats = feats2; buf = g2buf; i = idx;     voff = 0;  }
    else if (idx < B) { known = known3; feats = feats3; buf = g3buf; i = idx - A; voff = 32; }
    else if (idx < C) { known = known4; feats = feats4; buf = g4buf; i = idx - B; voff = 64; }
    else if (idx < D) {
        int i2 = idx - C;
        float x = matchp[3 * i2 + 0];
        float y = matchp[3 * i2 + 1];
        float z = matchp[3 * i2 + 2];
        float kk = __fadd_rn(__fadd_rn(__fmul_rn(x, x), __fmul_rn(y, y)), __fmul_rn(z, z));
        int base = (i2 >> 2) * 16 + (i2 & 3);
        gmbuf[base + 0] = x; gmbuf[base + 4] = y;
        gmbuf[base + 8] = z; gmbuf[base + 12] = kk;
        return;
    } else return;

    float x = known[3 * i + 0];
    float y = known[3 * i + 1];
    float z = known[3 * i + 2];
    // same rounding order as jnp.sum(known*known, -1)
    float kk = __fadd_rn(__fadd_rn(__fmul_rn(x, x), __fmul_rn(y, y)), __fmul_rn(z, z));

    float acc = 0.f;
    const float4* f4 = reinterpret_cast<const float4*>(feats + (size_t)i * Cc);
#pragma unroll
    for (int j = 0; j < 8; j++) {
        float4 tt = f4[j];
        acc = fmaf(tt.x, sv[voff + 4 * j + 0], acc);
        acc = fmaf(tt.y, sv[voff + 4 * j + 1], acc);
        acc = fmaf(tt.z, sv[voff + 4 * j + 2], acc);
        acc = fmaf(tt.w, sv[voff + 4 * j + 3], acc);
    }
    int base = (i >> 2) * 20 + (i & 3);
    buf[base + 0]  = x;  buf[base + 4]  = y;
    buf[base + 8]  = z;  buf[base + 12] = kk;
    buf[base + 16] = acc;
}

// ---------------- top-3 maintenance (short branchy nest, rare) --------------
__device__ __forceinline__ void try_ins(float e, float fv, float t[3], float f[3]) {
    if (e < t[2]) {
        if (e < t[1]) {
            t[2] = t[1]; f[2] = f[1];
            if (e < t[0]) { t[1] = t[0]; f[1] = f[0]; t[0] = e; f[0] = fv; }
            else          { t[1] = e;    f[1] = fv; }
        } else { t[2] = e; f[2] = fv; }
    }
}

// ---------------- interp scan: top-3 of d = (qq+kk) - 2*dot -----------------
// rounding order matches reference: s = qq+kk, then fma x, y, z
__device__ __forceinline__ void scan_set(
    const float* __restrict__ buf, int grp0, int Mg,
    const u64 c2x[Q], const u64 c2y[Q], const u64 c2z[Q], const u64 qq2[Q],
    float t[Q][3], float f[Q][3])
{
#pragma unroll
    for (int j = 0; j < Q; j++) {
        t[j][0] = t[j][1] = t[j][2] = BIG;
        f[j][0] = f[j][1] = f[j][2] = 0.f;
    }
    const char* p = reinterpret_cast<const char*>(buf) + (size_t)grp0 * 80;
#pragma unroll 2
    for (int g = 0; g < Mg; g++, p += 80) {
        ulonglong2 X = __ldg(reinterpret_cast<const ulonglong2*>(p));
        ulonglong2 Y = __ldg(reinterpret_cast<const ulonglong2*>(p + 16));
        ulonglong2 Z = __ldg(reinterpret_cast<const ulonglong2*>(p + 32));
        ulonglong2 W = __ldg(reinterpret_cast<const ulonglong2*>(p + 48));
        float4     F = __ldg(reinterpret_cast<const float4*>(p + 64));
#pragma unroll
        for (int j = 0; j < Q; j++) {
            u64 dl = ffma2u(c2x[j], X.x, fadd2u(qq2[j], W.x));
            dl = ffma2u(c2y[j], Y.x, dl);
            dl = ffma2u(c2z[j], Z.x, dl);
            u64 dh = ffma2u(c2x[j], X.y, fadd2u(qq2[j], W.y));
            dh = ffma2u(c2y[j], Y.y, dh);
            dh = ffma2u(c2z[j], Z.y, dh);
            float d0 = lo_(dl), d1 = hi_(dl), d2 = lo_(dh), d3 = hi_(dh);
            float m = fminf(fminf(d0, d1), fminf(d2, d3));
            if (m < t[j][2]) {                    // rare after warm-up
                try_ins(d0, F.x, t[j], f[j]);
                try_ins(d1, F.y, t[j], f[j]);
                try_ins(d2, F.z, t[j], f[j]);
                try_ins(d3, F.w, t[j], f[j]);
            }
        }
    }
}

// ---------------- mask scan: any(d2 < 0.25), margin + exact recheck ---------
__device__ __forceinline__ void scan_mask(
    const float* __restrict__ buf, int grp0, int Mg,
    const u64 c2x[Q], const u64 c2y[Q], const u64 c2z[Q], const u64 qq2[Q],
    bool found[Q])
{
    float tf[Q], qx[Q], qy[Q], qz[Q], qqv[Q];
#pragma unroll
    for (int j = 0; j < Q; j++) {
        found[j] = false;
        qqv[j] = lo_(qq2[j]);
        tf[j]  = 0.3125f - qqv[j];               // e < 0.25 + 0.0625 margin
        qx[j]  = -0.5f * lo_(c2x[j]);            // exact (pow2 scale)
        qy[j]  = -0.5f * lo_(c2y[j]);
        qz[j]  = -0.5f * lo_(c2z[j]);
    }
    const char* p = reinterpret_cast<const char*>(buf) + (size_t)grp0 * 64;
#pragma unroll 2
    for (int g = 0; g < Mg; g++, p += 64) {
        ulonglong2 X = __ldg(reinterpret_cast<const ulonglong2*>(p));
        ulonglong2 Y = __ldg(reinterpret_cast<const ulonglong2*>(p + 16));
        ulonglong2 Z = __ldg(reinterpret_cast<const ulonglong2*>(p + 32));
        ulonglong2 W = __ldg(reinterpret_cast<const ulonglong2*>(p + 48));
#pragma unroll
        for (int j = 0; j < Q; j++) {
            // fast path: e = kk - 2*dot (qq deferred; protected by margin)
            u64 el = ffma2u(c2x[j], X.x, ffma2u(c2y[j], Y.x, ffma2u(c2z[j], Z.x, W.x)));
            u64 eh = ffma2u(c2x[j], X.y, ffma2u(c2y[j], Y.y, ffma2u(c2z[j], Z.y, W.y)));
            float m = fminf(fminf(lo_(el), hi_(el)), fminf(lo_(eh), hi_(eh)));
            if (m < tf[j]) {                      // rare: exact recheck
                float cx[4] = { lo_(X.x), hi_(X.x), lo_(X.y), hi_(X.y) };
                float cy[4] = { lo_(Y.x), hi_(Y.x), lo_(Y.y), hi_(Y.y) };
                float cz[4] = { lo_(Z.x), hi_(Z.x), lo_(Z.y), hi_(Z.y) };
                float cw[4] = { lo_(W.x), hi_(W.x), lo_(W.y), hi_(W.y) };
#pragma unroll
                for (int c = 0; c < 4; c++) {
                    // bit-exact reference-mimic rounding
                    float dot = __fadd_rn(__fadd_rn(__fmul_rn(qx[j], cx[c]),
                                                    __fmul_rn(qy[j], cy[c])),
                                          __fmul_rn(qz[j], cz[c]));
                    float d = __fsub_rn(__fadd_rn(qqv[j], cw[c]),
                                        __fadd_rn(dot, dot));
                    if (d < 0.25f) found[j] = true;
                }
            }
        }
    }
}

// ---------------- merge 24 partial top-3 entries -----------------------------
__device__ __forceinline__ float merge_one(const float2* __restrict__ ent) {
    float t[3] = {BIG, BIG, BIG}, f[3] = {0.f, 0.f, 0.f};
#pragma unroll
    for (int k = 0; k < PARTS * 3; k++) {
        float2 c = ent[k];
        try_ins(c.x, c.y, t, f);
    }
    float d0 = fmaxf(t[0], 0.f);
    float d1 = fmaxf(t[1], 0.f);
    float d2 = fmaxf(t[2], 0.f);
    float r0 = 1.f / (d0 + 1e-8f);
    float r1 = 1.f / (d1 + 1e-8f);
    float r2 = 1.f / (d2 + 1e-8f);
    return fmaf(r0, f[0], fmaf(r1, f[1], r2 * f[2])) / (r0 + r1 + r2);
}

// ---------------- fused main kernel -----------------------------------------
// grid = 512 blocks; with <=64 regs all 512 are co-resident (4 per SM): one wave
__global__ void __launch_bounds__(NT, 4)
fused_kernel(const float* __restrict__ pts, float* __restrict__ out) {
    __shared__ float2 s_m[QPB * PARTS * 3];      // 12 KB merge scratch

    const int tid  = threadIdx.x;
    const int lane = tid & 31;
    const int part = tid >> 5;                   // warp id == candidate part
    const int b    = (blockIdx.x * QPB) >> 13;   // batch

    u64 c2x[Q], c2y[Q], c2z[Q], qq2[Q];
#pragma unroll
    for (int j = 0; j < Q; j++) {
        int gq = blockIdx.x * QPB + j * 32 + lane;
        float x = pts[3 * gq + 0];
        float y = pts[3 * gq + 1];
        float z = pts[3 * gq + 2];
        float qq = __fadd_rn(__fadd_rn(__fmul_rn(x, x), __fmul_rn(y, y)),
                             __fmul_rn(z, z));
        c2x[j] = dup2(-2.f * x);
        c2y[j] = dup2(-2.f * y);
        c2z[j] = dup2(-2.f * z);
        qq2[j] = dup2(qq);
    }

    float pred = 0.f;                            // meaningful for tid < QPB
    float t[Q][3], f[Q][3];

    const float* sb[3] = { g2buf, g3buf, g4buf };
    const int    sM[3] = { M2, M3, M4 };

#pragma unroll 1
    for (int s = 0; s < 3; s++) {
        const int Mg = sM[s] / (4 * PARTS);      // groups per part
        const int grp0 = (b * sM[s]) / 4 + part * Mg;
        scan_set(sb[s], grp0, Mg, c2x, c2y, c2z, qq2, t, f);
#pragma unroll
        for (int j = 0; j < Q; j++) {
            int q = j * 32 + lane;
            int bse = (q * PARTS + part) * 3;
            s_m[bse + 0] = make_float2(t[j][0], f[j][0]);
            s_m[bse + 1] = make_float2(t[j][1], f[j][1]);
            s_m[bse + 2] = make_float2(t[j][2], f[j][2]);
        }
        __syncthreads();
        if (tid < QPB) pred += merge_one(s_m + tid * PARTS * 3);
        __syncthreads();
    }

    bool found[Q];
    {
        const int Mg = MM / (4 * PARTS);
        const int grp0 = (b * MM) / 4 + part * Mg;
        scan_mask(gmbuf, grp0, Mg, c2x, c2y, c2z, qq2, found);
    }

    float* s_fl = reinterpret_cast<float*>(s_m);
#pragma unroll
    for (int j = 0; j < Q; j++)
        s_fl[(j * 32 + lane) * PARTS + part] = found[j] ? 1.f : 0.f;
    __syncthreads();
    if (tid < QPB) {
        float fl = 0.f;
#pragma unroll
        for (int k = 0; k < PARTS; k++) fl = fmaxf(fl, s_fl[tid * PARTS + k]);
        int gq = blockIdx.x * QPB + tid;
        out[gq] = pred;                          // pred_hm (B,N,1)
        out[Bn * Nn + gq] = fl;                  // gt_hm   (B,N)
    }
}

// ---------------- launch ----------------------------------------------------
extern "C" void kernel_launch(void* const* d_in, const int* in_sizes, int n_in,
                              void* d_out, int out_size) {
    (void)in_sizes; (void)n_in; (void)out_size;
    const float* pts    = (const float*)d_in[0];
    const float* known2 = (const float*)d_in[1];
    const float* feats2 = (const float*)d_in[2];
    const float* known3 = (const float*)d_in[3];
    const float* feats3 = (const float*)d_in[4];
    const float* known4 = (const float*)d_in[5];
    const float* feats4 = (const float*)d_in[6];
    const float* matchp = (const float*)d_in[7];
    const float* w_fc   = (const float*)d_in[8];
    const float* w_cls  = (const float*)d_in[9];
    float* out = (float*)d_out;

    constexpr int total = Bn * (M2 + M3 + M4 + MM);
    precompute_kernel<<<(total + NT - 1) / NT, NT>>>(
        known2, feats2, known3, feats3, known4, feats4, matchp, w_fc, w_cls);
    fused_kernel<<<(Bn * Nn) / QPB, NT>>>(pts, out);
}

// round 9
// speedup vs baseline: 1.6978x; 1.1049x over previous
#include <cuda_runtime.h>

using u64 = unsigned long long;

// ---------------- problem constants -----------------------------------------
constexpr int Bn = 4;
constexpr int Nn = 8192;
constexpr int M2 = 8192;
constexpr int M3 = 4096;
constexpr int M4 = 2048;
constexpr int MM = 4096;

constexpr int NB = 128;            // x bins
constexpr float XMIN = -64.f;
constexpr float WBIN = 1.0f;
constexpr float BIG  = 3.0e38f;
constexpr float MARG = 0.0625f;    // expansion margin >> fp error of d
constexpr unsigned FULL = 0xFFFFFFFFu;
constexpr int TOTAL_ELEMS = Bn * (M2 + M3 + M4 + MM + Nn);   // 106496

// ---------------- device scratch ---------------------------------------------
// interp record per 4-cand group: [x4|y4|z4|kk4|fv4] = 80 B; mask: 64 B
__device__ __align__(16) float g2buf[Bn * M2 * 5];
__device__ __align__(16) float g3buf[Bn * M3 * 5];
__device__ __align__(16) float g4buf[Bn * M4 * 5];
__device__ __align__(16) float gmbuf[Bn * MM * 4];
__device__ float qsx[Bn * Nn], qsy[Bn * Nn], qsz[Bn * Nn];
__device__ int   qsi[Bn * Nn];
__device__ int   gcnt[20 * NB];            // arr = set(0..2)*4+b | 12+b | 16+b
__device__ int   gfil[20 * NB];
__device__ int   goffs[20 * (NB + 1)];
__device__ float g_v[96];

// ---------------- packed f32x2 helpers ----------------------------------------
__device__ __forceinline__ u64 ffma2u(u64 a, u64 b, u64 c) {
    u64 r;
    asm("fma.rn.f32x2 %0, %1, %2, %3;" : "=l"(r) : "l"(a), "l"(b), "l"(c));
    return r;
}
__device__ __forceinline__ u64 fadd2u(u64 a, u64 b) {
    u64 r;
    asm("add.rn.f32x2 %0, %1, %2;" : "=l"(r) : "l"(a), "l"(b));
    return r;
}
__device__ __forceinline__ float lo_(u64 v) { return __uint_as_float((unsigned)v); }
__device__ __forceinline__ float hi_(u64 v) { return __uint_as_float((unsigned)(v >> 32)); }
__device__ __forceinline__ u64 dup2(float x) {
    unsigned b = __float_as_uint(x);
    return ((u64)b << 32) | (u64)b;
}
__device__ __forceinline__ int bin_of(float x) {
    int b = (int)(x - XMIN);
    return min(max(b, 0), NB - 1);
}

// ---------------- element decode ----------------------------------------------
__device__ __forceinline__ void decode(int idx, int& arr, int& il, int& flat) {
    if (idx < 32768)      { arr = (idx >> 13);           il = idx & 8191; flat = idx; }
    else if (idx < 49152) { int j = idx - 32768; arr = 4  + (j >> 12); il = j & 4095; flat = j; }
    else if (idx < 57344) { int j = idx - 49152; arr = 8  + (j >> 11); il = j & 2047; flat = j; }
    else if (idx < 73728) { int j = idx - 57344; arr = 12 + (j >> 12); il = j & 4095; flat = j; }
    else                  { int j = idx - 73728; arr = 16 + (j >> 13); il = j & 8191; flat = j; }
}
__device__ __forceinline__ const float* src_of(int arr,
    const float* k2, const float* k3, const float* k4,
    const float* mp, const float* pt)
{
    if (arr < 4)  return k2;
    if (arr < 8)  return k3;
    if (arr < 12) return k4;
    if (arr < 16) return mp;
    return pt;
}

// ---------------- K0: zero counters -------------------------------------------
__global__ void zero_kernel() {
    int i = blockIdx.x * 256 + threadIdx.x;
    if (i < 20 * NB) { gcnt[i] = 0; gfil[i] = 0; }
}

// ---------------- K1: histogram + g_v ------------------------------------------
__global__ void hist_kernel(const float* __restrict__ k2, const float* __restrict__ k3,
    const float* __restrict__ k4, const float* __restrict__ mp,
    const float* __restrict__ pt,
    const float* __restrict__ w_fc, const float* __restrict__ w_cls)
{
    int idx = blockIdx.x * 256 + threadIdx.x;
    if (blockIdx.x == 0 && threadIdx.x < 96) {
        float acc = 0.f;
#pragma unroll
        for (int k = 0; k < 64; k++)
            acc = fmaf(w_cls[k], w_fc[k * 96 + threadIdx.x], acc);
        g_v[threadIdx.x] = acc;
    }
    if (idx >= TOTAL_ELEMS) return;
    int arr, il, flat;
    decode(idx, arr, il, flat);
    const float* src = src_of(arr, k2, k3, k4, mp, pt);
    atomicAdd(&gcnt[arr * NB + bin_of(src[flat * 3])], 1);
}

// ---------------- K2: per-array exclusive prefix sums ---------------------------
__global__ void prefix_kernel() {
    int w = threadIdx.x >> 5, lane = threadIdx.x & 31;
    if (w >= 20) return;
    int run = 0;
    for (int c0 = 0; c0 < NB; c0 += 32) {
        int bb = c0 + lane;
        int c = gcnt[w * NB + bb];
        int v = c;
#pragma unroll
        for (int o = 1; o < 32; o <<= 1) {
            int u = __shfl_up_sync(FULL, v, o);
            if (lane >= o) v += u;
        }
        goffs[w * (NB + 1) + bb] = run + v - c;
        run += __shfl_sync(FULL, v, 31);
    }
    if (lane == 0) goffs[w * (NB + 1) + NB] = run;
}

// ---------------- K3: scatter into binned records --------------------------------
__global__ void scatter_kernel(const float* __restrict__ k2, const float* __restrict__ f2,
    const float* __restrict__ k3, const float* __restrict__ f3,
    const float* __restrict__ k4, const float* __restrict__ f4,
    const float* __restrict__ mp, const float* __restrict__ pt)
{
    int idx = blockIdx.x * 256 + threadIdx.x;
    if (idx >= TOTAL_ELEMS) return;
    int arr, il, flat;
    decode(idx, arr, il, flat);
    const float* src = src_of(arr, k2, k3, k4, mp, pt);
    float x = src[flat * 3 + 0];
    float y = src[flat * 3 + 1];
    float z = src[flat * 3 + 2];
    // same rounding order as jnp.sum(p*p, -1)
    float kk = __fadd_rn(__fadd_rn(__fmul_rn(x, x), __fmul_rn(y, y)), __fmul_rn(z, z));
    int bb = bin_of(x);
    int pos = goffs[arr * (NB + 1) + bb] + atomicAdd(&gfil[arr * NB + bb], 1);
    int b = arr & 3;

    if (arr < 12) {
        const float* feats; int voff; float* buf; int Ms;
        if (arr < 4)      { feats = f2; voff = 0;  buf = g2buf; Ms = M2; }
        else if (arr < 8) { feats = f3; voff = 32; buf = g3buf; Ms = M3; }
        else              { feats = f4; voff = 64; buf = g4buf; Ms = M4; }
        float acc = 0.f;
        const float4* fp = reinterpret_cast<const float4*>(feats + (size_t)flat * 32);
#pragma unroll
        for (int j = 0; j < 8; j++) {
            float4 t = fp[j];
            acc = fmaf(t.x, g_v[voff + 4 * j + 0], acc);
            acc = fmaf(t.y, g_v[voff + 4 * j + 1], acc);
            acc = fmaf(t.z, g_v[voff + 4 * j + 2], acc);
            acc = fmaf(t.w, g_v[voff + 4 * j + 3], acc);
        }
        int eg = b * Ms + pos;
        float* gp = buf + (size_t)(eg >> 2) * 20;
        int sl = eg & 3;
        gp[sl] = x; gp[4 + sl] = y; gp[8 + sl] = z; gp[12 + sl] = kk; gp[16 + sl] = acc;
    } else if (arr < 16) {
        int eg = b * MM + pos;
        float* gp = gmbuf + (size_t)(eg >> 2) * 16;
        int sl = eg & 3;
        gp[sl] = x; gp[4 + sl] = y; gp[8 + sl] = z; gp[12 + sl] = kk;
    } else {
        int o = b * Nn + pos;
        qsx[o] = x; qsy[o] = y; qsz[o] = z;
        qsi[o] = b * Nn + il;                      // original global query index
    }
}

// ---------------- top-3 maintenance ----------------------------------------------
__device__ __forceinline__ void try_ins(float e, float fv,
                                        float& t0, float& t1, float& t2,
                                        float& f0, float& f1, float& f2) {
    if (e < t2) {
        if (e < t1) {
            t2 = t1; f2 = f1;
            if (e < t0) { t1 = t0; f1 = f0; t0 = e; f0 = fv; }
            else        { t1 = e;  f1 = fv; }
        } else { t2 = e; f2 = fv; }
    }
}

// one 4-cand group, interp: d = (qq+kk) - 2*dot (reference rounding order)
__device__ __forceinline__ void scan_group_i(const float* buf, int g,
    u64 c2x, u64 c2y, u64 c2z, u64 qq2,
    float& t0, float& t1, float& t2, float& f0, float& f1, float& f2)
{
    const char* p = reinterpret_cast<const char*>(buf) + (size_t)g * 80;
    ulonglong2 X = __ldg(reinterpret_cast<const ulonglong2*>(p));
    ulonglong2 Y = __ldg(reinterpret_cast<const ulonglong2*>(p + 16));
    ulonglong2 Z = __ldg(reinterpret_cast<const ulonglong2*>(p + 32));
    ulonglong2 W = __ldg(reinterpret_cast<const ulonglong2*>(p + 48));
    float4     F = __ldg(reinterpret_cast<const float4*>(p + 64));
    u64 dl = fadd2u(qq2, W.x);
    dl = ffma2u(c2x, X.x, dl); dl = ffma2u(c2y, Y.x, dl); dl = ffma2u(c2z, Z.x, dl);
    u64 dh = fadd2u(qq2, W.y);
    dh = ffma2u(c2x, X.y, dh); dh = ffma2u(c2y, Y.y, dh); dh = ffma2u(c2z, Z.y, dh);
    float d0 = lo_(dl), d1 = hi_(dl), d2 = lo_(dh), d3 = hi_(dh);
    float m = fminf(fminf(d0, d1), fminf(d2, d3));
    if (m < t2) {
        try_ins(d0, F.x, t0, t1, t2, f0, f1, f2);
        try_ins(d1, F.y, t0, t1, t2, f0, f1, f2);
        try_ins(d2, F.z, t0, t1, t2, f0, f1, f2);
        try_ins(d3, F.w, t0, t1, t2, f0, f1, f2);
    }
}

// ---------------- K4: scan (4 lanes/query, 8 sorted queries/warp) ----------------
__global__ void __launch_bounds__(256)
scan_kernel(float* __restrict__ out) {
    const int W    = blockIdx.x * 8 + (threadIdx.x >> 5);
    const int lane = threadIdx.x & 31;
    const int sub  = lane & 3;
    const int b    = W >> 10;
    const int qo   = b * Nn + (W & 1023) * 8 + (lane >> 2);

    const float x = qsx[qo], y = qsy[qo], z = qsz[qo];
    const int   oi = qsi[qo];
    const float qq = __fadd_rn(__fadd_rn(__fmul_rn(x, x), __fmul_rn(y, y)),
                               __fmul_rn(z, z));
    const u64 c2x = dup2(-2.f * x), c2y = dup2(-2.f * y), c2z = dup2(-2.f * z);
    const u64 qq2 = dup2(qq);

    // warp-shared bin window
    int cb = bin_of(x);
    int cmin = cb, cmax = cb;
#pragma unroll
    for (int o = 16; o; o >>= 1) {
        cmin = min(cmin, __shfl_xor_sync(FULL, cmin, o));
        cmax = max(cmax, __shfl_xor_sync(FULL, cmax, o));
    }

    float pred = 0.f;
    const float* bufs[3] = { g2buf, g3buf, g4buf };
    const int    Msv[3]  = { M2, M3, M4 };

#pragma unroll 1
    for (int s = 0; s < 3; s++) {
        const float* buf = bufs[s];
        const int* offs = goffs + (s * 4 + b) * (NB + 1);
        const int gb0 = (b * Msv[s]) >> 2;             // batch group base
        float t0 = BIG, t1 = BIG, t2 = BIG, f0 = 0.f, f1 = 0.f, f2 = 0.f;

        int bl = max(cmin - 1, 0), bh = min(cmax + 1, NB - 1);
        int gslo = gb0 + (__ldg(offs + bl) >> 2);
        int gshi = gb0 + ((__ldg(offs + bh + 1) + 3) >> 2);
#pragma unroll 2
        for (int g = gslo + sub; g < gshi; g += 4)
            scan_group_i(buf, g, c2x, c2y, c2z, qq2, t0, t1, t2, f0, f1, f2);

        while (true) {
            float eL = XMIN + bl * WBIN;               // unscanned left: x <= eL
            float eR = XMIN + (bh + 1) * WBIN;         // unscanned right: x >= eR
            float dL = x - eL, dR = eR - x;
            bool nL = (bl > 0)      && (dL * dL < t2 + MARG);
            bool nR = (bh < NB - 1) && (dR * dR < t2 + MARG);
            unsigned mL = __ballot_sync(FULL, nL);
            unsigned mR = __ballot_sync(FULL, nR);
            if (!mL && !mR) break;
            if (mL) {
                bl--;
                int nlo = gb0 + (__ldg(offs + bl) >> 2);
                for (int g = nlo + sub; g < gslo; g += 4)
                    scan_group_i(buf, g, c2x, c2y, c2z, qq2, t0, t1, t2, f0, f1, f2);
                gslo = nlo;
            }
            if (mR) {
                bh++;
                int nhi = gb0 + ((__ldg(offs + bh + 1) + 3) >> 2);
                for (int g = gshi + sub; g < nhi; g += 4)
                    scan_group_i(buf, g, c2x, c2y, c2z, qq2, t0, t1, t2, f0, f1, f2);
                gshi = nhi;
            }
        }

        // butterfly merge across the 4 sub-lanes of this query
#pragma unroll
        for (int o = 1; o <= 2; o <<= 1) {
            float rt0 = __shfl_xor_sync(FULL, t0, o), rf0 = __shfl_xor_sync(FULL, f0, o);
            float rt1 = __shfl_xor_sync(FULL, t1, o), rf1 = __shfl_xor_sync(FULL, f1, o);
            float rt2 = __shfl_xor_sync(FULL, t2, o), rf2 = __shfl_xor_sync(FULL, f2, o);
            try_ins(rt0, rf0, t0, t1, t2, f0, f1, f2);
            try_ins(rt1, rf1, t0, t1, t2, f0, f1, f2);
            try_ins(rt2, rf2, t0, t1, t2, f0, f1, f2);
        }
        float d0 = fmaxf(t0, 0.f), d1 = fmaxf(t1, 0.f), d2c = fmaxf(t2, 0.f);
        float r0 = 1.f / (d0 + 1e-8f);
        float r1 = 1.f / (d1 + 1e-8f);
        float r2 = 1.f / (d2c + 1e-8f);
        pred += fmaf(r0, f0, fmaf(r1, f1, r2 * f2)) / (r0 + r1 + r2);
    }

    // ---- mask: any(d2 < 0.25) over bins [cmin-1, cmax+1] (covers each +-1) ----
    int found = 0;
    {
        const int* offs = goffs + (12 + b) * (NB + 1);
        const int gb0 = (b * MM) >> 2;
        int bl = max(cmin - 1, 0), bh = min(cmax + 1, NB - 1);
        int gs = gb0 + (__ldg(offs + bl) >> 2);
        int ge = gb0 + ((__ldg(offs + bh + 1) + 3) >> 2);
        float tf = 0.3125f - qq;                       // margin fast path
#pragma unroll 2
        for (int g = gs + sub; g < ge; g += 4) {
            const char* p = reinterpret_cast<const char*>(gmbuf) + (size_t)g * 64;
            ulonglong2 X = __ldg(reinterpret_cast<const ulonglong2*>(p));
            ulonglong2 Y = __ldg(reinterpret_cast<const ulonglong2*>(p + 16));
            ulonglong2 Z = __ldg(reinterpret_cast<const ulonglong2*>(p + 32));
            ulonglong2 W = __ldg(reinterpret_cast<const ulonglong2*>(p + 48));
            u64 el = ffma2u(c2x, X.x, ffma2u(c2y, Y.x, ffma2u(c2z, Z.x, W.x)));
            u64 eh = ffma2u(c2x, X.y, ffma2u(c2y, Y.y, ffma2u(c2z, Z.y, W.y)));
            float m = fminf(fminf(lo_(el), hi_(el)), fminf(lo_(eh), hi_(eh)));
            if (m < tf) {                              // rare: exact recheck
                float cx[4] = { lo_(X.x), hi_(X.x), lo_(X.y), hi_(X.y) };
                float cy[4] = { lo_(Y.x), hi_(Y.x), lo_(Y.y), hi_(Y.y) };
                float cz[4] = { lo_(Z.x), hi_(Z.x), lo_(Z.y), hi_(Z.y) };
                float cw[4] = { lo_(W.x), hi_(W.x), lo_(W.y), hi_(W.y) };
#pragma unroll
                for (int c = 0; c < 4; c++) {
                    // bit-exact reference-mimic rounding
                    float dot = __fadd_rn(__fadd_rn(__fmul_rn(x, cx[c]),
                                                    __fmul_rn(y, cy[c])),
                                          __fmul_rn(z, cz[c]));
                    float d = __fsub_rn(__fadd_rn(qq, cw[c]), __fadd_rn(dot, dot));
                    if (d < 0.25f) found = 1;
                }
            }
        }
        found |= __shfl_xor_sync(FULL, found, 1);
        found |= __shfl_xor_sync(FULL, found, 2);
    }

    if (sub == 0) {
        out[oi] = pred;                                // pred_hm (B,N,1)
        out[Bn * Nn + oi] = found ? 1.f : 0.f;         // gt_hm   (B,N)
    }
}

// ---------------- launch ----------------------------------------------------------
extern "C" void kernel_launch(void* const* d_in, const int* in_sizes, int n_in,
                              void* d_out, int out_size) {
    (void)in_sizes; (void)n_in; (void)out_size;
    const float* pts    = (const float*)d_in[0];
    const float* known2 = (const float*)d_in[1];
    const float* feats2 = (const float*)d_in[2];
    const float* known3 = (const float*)d_in[3];
    const float* feats3 = (const float*)d_in[4];
    const float* known4 = (const float*)d_in[5];
    const float* feats4 = (const float*)d_in[6];
    const float* matchp = (const float*)d_in[7];
    const float* w_fc   = (const float*)d_in[8];
    const float* w_cls  = (const float*)d_in[9];
    float* out = (float*)d_out;

    const int eb = (TOTAL_ELEMS + 255) / 256;
    zero_kernel<<<(20 * NB + 255) / 256, 256>>>();
    hist_kernel<<<eb, 256>>>(known2, known3, known4, matchp, pts, w_fc, w_cls);
    prefix_kernel<<<1, 640>>>();
    scatter_kernel<<<eb, 256>>>(known2, feats2, known3, feats3,
                                known4, feats4, matchp, pts);
    scan_kernel<<<(Bn * Nn) / 64, 256>>>(out);         // 4 lanes/query
}